// round 4
// baseline (speedup 1.0000x reference)
#include <cuda_runtime.h>

#define NN    10000
#define EE    160000
#define INDIM 1000
#define HID   256
#define OUTD  2

// ---------------- scratch (static __device__, no runtime alloc) ----------------
__device__ float g_xw1[NN * HID];   // features @ W1
__device__ float g_h[NN * HID];     // relu(gcn1)
__device__ float g_hw2[NN * OUTD];  // h @ W2
__device__ float g_dinv[NN];
__device__ float g_sq[NN];
__device__ int   g_deg[NN];
__device__ int   g_cur[NN];
__device__ int   g_off[NN + 1];
__device__ int   g_srcv[EE];

// ---------------- CSR build ----------------
__global__ void k_zero_deg() {
    int i = blockIdx.x * blockDim.x + threadIdx.x;
    if (i < NN) g_deg[i] = 0;
}

__global__ void k_count(const int* __restrict__ ei) {
    int e = blockIdx.x * blockDim.x + threadIdx.x;
    if (e < EE) atomicAdd(&g_deg[ei[EE + e]], 1);
}

// single-block scan over 10000 counts; also computes dinv = rsqrt(indeg+1)
__global__ void k_scan() {
    __shared__ int part[256];
    __shared__ int excl[257];
    int t = threadIdx.x;
    const int CH = (NN + 255) / 256;  // 40
    int base = t * CH;
    int s = 0;
    for (int i = 0; i < CH; i++) {
        int idx = base + i;
        if (idx < NN) s += g_deg[idx];
    }
    part[t] = s;
    __syncthreads();
    if (t == 0) {
        int run = 0;
        for (int i = 0; i < 256; i++) { excl[i] = run; run += part[i]; }
        excl[256] = run;
    }
    __syncthreads();
    int off = excl[t];
    for (int i = 0; i < CH; i++) {
        int idx = base + i;
        if (idx < NN) {
            g_off[idx] = off;
            g_cur[idx] = off;
            int d = g_deg[idx];
            off += d;
            g_dinv[idx] = rsqrtf((float)(d + 1));  // +1 self loop
        }
    }
    if (t == 255) g_off[NN] = excl[256];
}

__global__ void k_scatter(const int* __restrict__ ei) {
    int e = blockIdx.x * blockDim.x + threadIdx.x;
    if (e < EE) {
        int d = ei[EE + e];
        int pos = atomicAdd(&g_cur[d], 1);
        g_srcv[pos] = ei[e];
    }
}

// ---------------- GEMM1: [NN,INDIM] x [INDIM,HID] -> g_xw1 ----------------
#define BM 128
#define BN 128
#define BK 8

__global__ __launch_bounds__(256) void k_gemm1(const float* __restrict__ A,
                                               const float* __restrict__ B) {
    __shared__ __align__(16) float As[BK][BM + 4];
    __shared__ __align__(16) float Bs[BK][BN];
    int tid = threadIdx.x;
    int bx = blockIdx.x, by = blockIdx.y;
    int tx = tid & 15, ty = tid >> 4;

    int arow = tid >> 1;
    int acol = (tid & 1) * 4;
    int brow = tid >> 5;
    int bcol = (tid & 31) * 4;

    int aRowG = by * BM + arow;
    const float* Aptr = A + (size_t)aRowG * INDIM + acol;
    const float* Bptr = B + (size_t)brow * HID + bx * BN + bcol;
    bool aValid = aRowG < NN;

    float c[8][8];
#pragma unroll
    for (int i = 0; i < 8; i++)
#pragma unroll
        for (int j = 0; j < 8; j++) c[i][j] = 0.0f;

    for (int k0 = 0; k0 < INDIM; k0 += BK) {
        float4 av = aValid ? *(const float4*)(Aptr + k0) : make_float4(0.f, 0.f, 0.f, 0.f);
        float4 bv = *(const float4*)(Bptr + (size_t)k0 * HID);
        As[acol + 0][arow] = av.x;
        As[acol + 1][arow] = av.y;
        As[acol + 2][arow] = av.z;
        As[acol + 3][arow] = av.w;
        *(float4*)&Bs[brow][bcol] = bv;
        __syncthreads();
#pragma unroll
        for (int kk = 0; kk < BK; kk++) {
            float a[8], b[8];
            *(float4*)(a)     = *(const float4*)&As[kk][ty * 8];
            *(float4*)(a + 4) = *(const float4*)&As[kk][ty * 8 + 4];
            *(float4*)(b)     = *(const float4*)&Bs[kk][tx * 8];
            *(float4*)(b + 4) = *(const float4*)&Bs[kk][tx * 8 + 4];
#pragma unroll
            for (int i = 0; i < 8; i++)
#pragma unroll
                for (int j = 0; j < 8; j++) c[i][j] = fmaf(a[i], b[j], c[i][j]);
        }
        __syncthreads();
    }
#pragma unroll
    for (int i = 0; i < 8; i++) {
        int row = by * BM + ty * 8 + i;
        if (row < NN) {
            float* cp = g_xw1 + (size_t)row * HID + bx * BN + tx * 8;
            *(float4*)cp = *(float4*)&c[i][0];
            *(float4*)(cp + 4) = *(float4*)&c[i][4];
        }
    }
}

// ---------------- agg1 + bias + relu -> g_h (warp per node) ----------------
__global__ void k_agg1(const float* __restrict__ b1) {
    int w = (blockIdx.x * blockDim.x + threadIdx.x) >> 5;
    int lane = threadIdx.x & 31;
    if (w >= NN) return;
    int i = w;
    float di = g_dinv[i];
    float acc[8];
    const float* xi = g_xw1 + (size_t)i * HID;
#pragma unroll
    for (int u = 0; u < 8; u++) acc[u] = di * xi[u * 32 + lane];  // self loop
    int p0 = g_off[i], p1 = g_off[i + 1];
    for (int p = p0; p < p1; p++) {
        int s = g_srcv[p];
        float ds = g_dinv[s];
        const float* xs = g_xw1 + (size_t)s * HID;
#pragma unroll
        for (int u = 0; u < 8; u++) acc[u] += ds * xs[u * 32 + lane];
    }
    float* hi = g_h + (size_t)i * HID;
#pragma unroll
    for (int u = 0; u < 8; u++) {
        int f = u * 32 + lane;
        hi[f] = fmaxf(fmaf(di, acc[u], b1[f]), 0.0f);
    }
}

// ---------------- h @ W2 -> g_hw2 (warp per node) ----------------
__global__ void k_hw2(const float* __restrict__ W2) {
    int w = (blockIdx.x * blockDim.x + threadIdx.x) >> 5;
    int lane = threadIdx.x & 31;
    if (w >= NN) return;
    const float* hi = g_h + (size_t)w * HID;
    float a0 = 0.f, a1 = 0.f;
#pragma unroll
    for (int u = 0; u < 8; u++) {
        int k = u * 32 + lane;
        float hv = hi[k];
        a0 = fmaf(hv, W2[k * 2 + 0], a0);
        a1 = fmaf(hv, W2[k * 2 + 1], a1);
    }
#pragma unroll
    for (int o = 16; o > 0; o >>= 1) {
        a0 += __shfl_down_sync(0xffffffffu, a0, o);
        a1 += __shfl_down_sync(0xffffffffu, a1, o);
    }
    if (lane == 0) {
        g_hw2[w * 2 + 0] = a0;
        g_hw2[w * 2 + 1] = a1;
    }
}

// ---------------- agg2 + bias -> emb (d_out) and sq ----------------
__global__ void k_agg2(const float* __restrict__ b2, float* __restrict__ emb) {
    int i = blockIdx.x * blockDim.x + threadIdx.x;
    if (i >= NN) return;
    float di = g_dinv[i];
    float a0 = di * g_hw2[i * 2 + 0];  // self loop
    float a1 = di * g_hw2[i * 2 + 1];
    int p0 = g_off[i], p1 = g_off[i + 1];
    for (int p = p0; p < p1; p++) {
        int s = g_srcv[p];
        float ds = g_dinv[s];
        a0 = fmaf(ds, g_hw2[s * 2 + 0], a0);
        a1 = fmaf(ds, g_hw2[s * 2 + 1], a1);
    }
    float e0 = fmaf(di, a0, b2[0]);
    float e1 = fmaf(di, a1, b2[1]);
    emb[i * 2 + 0] = e0;
    emb[i * 2 + 1] = e1;
    g_sq[i] = e0 * e0 + e1 * e1;
}

// ---------------- q matrix: q = 1/(1 + 0.5*dist) ----------------
#define TJ 1024
#define TI 16

__device__ __forceinline__ float qval(float d2) {
    float d2c = fmaxf(d2, 1e-30f);          // avoid 0*inf; sqrt(1e-30)~1e-15 -> q~1
    float dist = d2c * rsqrtf(d2c);         // approx sqrt: 1 MUFU + 1 FMUL
    return __fdividef(1.0f, fmaf(0.5f, dist, 1.0f));
}

__global__ __launch_bounds__(256) void k_q(const float* __restrict__ emb,
                                           float* __restrict__ q) {
    __shared__ float sx[TJ], sy[TJ], ss[TJ];
    int j0 = blockIdx.x * TJ;
    int i0 = blockIdx.y * TI;
    int t = threadIdx.x;
#pragma unroll
    for (int v = 0; v < 4; v++) {
        int jl = t + v * 256;
        int jj = j0 + jl;
        if (jj < NN) {
            sx[jl] = emb[jj * 2 + 0];
            sy[jl] = emb[jj * 2 + 1];
            ss[jl] = g_sq[jj];
        }
    }
    __syncthreads();
    int jl = t * 4;
    int j = j0 + jl;
    if (j >= NN) return;
    float x0 = sx[jl], x1 = sx[jl + 1], x2 = sx[jl + 2], x3 = sx[jl + 3];
    float y0 = sy[jl], y1 = sy[jl + 1], y2 = sy[jl + 2], y3 = sy[jl + 3];
    float s0 = ss[jl], s1 = ss[jl + 1], s2 = ss[jl + 2], s3 = ss[jl + 3];
#pragma unroll
    for (int r = 0; r < TI; r++) {
        int i = i0 + r;
        float ex = emb[i * 2 + 0];
        float ey = emb[i * 2 + 1];
        float si = g_sq[i];
        float4 o;
        o.x = qval(si + s0 - 2.0f * fmaf(ex, x0, ey * y0));
        o.y = qval(si + s1 - 2.0f * fmaf(ex, x1, ey * y1));
        o.z = qval(si + s2 - 2.0f * fmaf(ex, x2, ey * y2));
        o.w = qval(si + s3 - 2.0f * fmaf(ex, x3, ey * y3));
        *(float4*)(q + (size_t)i * NN + j) = o;
    }
}

// ---------------- launch ----------------
extern "C" void kernel_launch(void* const* d_in, const int* in_sizes, int n_in,
                              void* d_out, int out_size) {
    const float* features = (const float*)d_in[0];
    const int*   ei       = (const int*)d_in[1];
    const float* W1       = (const float*)d_in[2];
    const float* b1       = (const float*)d_in[3];
    const float* W2       = (const float*)d_in[4];
    const float* b2       = (const float*)d_in[5];
    float* out = (float*)d_out;
    float* emb = out;                 // [NN, 2]
    float* q   = out + NN * OUTD;     // [NN, NN]

    k_zero_deg<<<(NN + 255) / 256, 256>>>();
    k_count<<<(EE + 255) / 256, 256>>>(ei);
    k_scan<<<1, 256>>>();
    k_scatter<<<(EE + 255) / 256, 256>>>(ei);

    dim3 g1(HID / BN, (NN + BM - 1) / BM);
    k_gemm1<<<g1, 256>>>(features, W1);

    k_agg1<<<(NN * 32 + 255) / 256, 256>>>(b1);
    k_hw2<<<(NN * 32 + 255) / 256, 256>>>(W2);
    k_agg2<<<(NN + 255) / 256, 256>>>(b2, emb);

    dim3 gq((NN + TJ - 1) / TJ, NN / TI);
    k_q<<<gq, 256>>>(emb, q);
}

// round 6
// speedup vs baseline: 2.8110x; 2.8110x over previous
#include <cuda_runtime.h>
#include <cstdint>

#define NN    10000
#define EE    160000
#define INDIM 1000
#define HID   256
#define OUTD  2

// ---------------- scratch (static __device__, no runtime alloc) ----------------
__device__ float g_xw1[NN * HID];   // features @ W1
__device__ float g_h[NN * HID];     // relu(gcn1)
__device__ float g_hw2[NN * OUTD];  // h @ W2
__device__ float g_dinv[NN];
__device__ float g_sq[NN];
__device__ int   g_deg[NN];
__device__ int   g_cur[NN];
__device__ int   g_off[NN + 1];
__device__ int   g_srcv[EE];

// ================= helpers =================
__device__ __forceinline__ uint32_t smem_u32(const void* p) {
    uint32_t a;
    asm("{ .reg .u64 t; cvta.to.shared.u64 t, %1; cvt.u32.u64 %0, t; }"
        : "=r"(a) : "l"(p));
    return a;
}

__device__ __forceinline__ void cp16(uint32_t dst, const void* src, int sz) {
    asm volatile("cp.async.cg.shared.global [%0], [%1], 16, %2;"
                 :: "r"(dst), "l"(src), "r"(sz) : "memory");
}

__device__ __forceinline__ uint32_t tf32r(float x) {
    uint32_t u;
    asm("cvt.rna.tf32.f32 %0, %1;" : "=r"(u) : "f"(x));
    return u;
}

__device__ __forceinline__ void mma_tf32(float* d, const uint32_t* a, const uint32_t* b) {
    asm volatile(
        "mma.sync.aligned.m16n8k8.row.col.f32.tf32.tf32.f32 "
        "{%0,%1,%2,%3}, {%4,%5,%6,%7}, {%8,%9}, {%0,%1,%2,%3};"
        : "+f"(d[0]), "+f"(d[1]), "+f"(d[2]), "+f"(d[3])
        : "r"(a[0]), "r"(a[1]), "r"(a[2]), "r"(a[3]), "r"(b[0]), "r"(b[1]));
}

// ---------------- CSR build ----------------
__global__ void k_zero_deg() {
    int i = blockIdx.x * blockDim.x + threadIdx.x;
    if (i < NN) g_deg[i] = 0;
}

__global__ void k_count(const int* __restrict__ ei) {
    int e = blockIdx.x * blockDim.x + threadIdx.x;
    if (e < EE) atomicAdd(&g_deg[ei[EE + e]], 1);
}

__global__ void k_scan() {
    __shared__ int part[256];
    __shared__ int excl[257];
    int t = threadIdx.x;
    const int CH = (NN + 255) / 256;
    int base = t * CH;
    int s = 0;
    for (int i = 0; i < CH; i++) {
        int idx = base + i;
        if (idx < NN) s += g_deg[idx];
    }
    part[t] = s;
    __syncthreads();
    if (t == 0) {
        int run = 0;
        for (int i = 0; i < 256; i++) { excl[i] = run; run += part[i]; }
        excl[256] = run;
    }
    __syncthreads();
    int off = excl[t];
    for (int i = 0; i < CH; i++) {
        int idx = base + i;
        if (idx < NN) {
            g_off[idx] = off;
            g_cur[idx] = off;
            int d = g_deg[idx];
            off += d;
            g_dinv[idx] = rsqrtf((float)(d + 1));
        }
    }
    if (t == 255) g_off[NN] = excl[256];
}

__global__ void k_scatter(const int* __restrict__ ei) {
    int e = blockIdx.x * blockDim.x + threadIdx.x;
    if (e < EE) {
        int d = ei[EE + e];
        int pos = atomicAdd(&g_cur[d], 1);
        g_srcv[pos] = ei[e];
    }
}

// ---------------- GEMM1 via mma.sync tf32: features[10000,1000] @ W1[1000,256] ----------------
// CTA tile M=64, N=128, K=16 per stage; 3-stage cp.async pipeline.
// SMEM per stage: A [64][20] floats (stride 20 -> conflict-free frag loads),
//                 B [16][136] floats (stride 136 -> conflict-free frag loads).
#define A_STRIDE 20
#define B_STRIDE 136
#define A_FLOATS (64 * A_STRIDE)              // 1280
#define STAGE_F  (A_FLOATS + 16 * B_STRIDE)   // 3456 floats = 13824 B
#define NCH      63                           // ceil(1000/16)

__device__ __forceinline__ void g1_load(float* smbase, int c, int ctaRow0, int n0,
                                        const float* __restrict__ A,
                                        const float* __restrict__ B) {
    if (c < NCH) {
        int k0 = c * 16;
        float* As = smbase + (c % 3) * STAGE_F;
        float* Bs = As + A_FLOATS;
        int tid = threadIdx.x;
        // A: 64 rows x 4 chunks of 16B -> 256 cp.async (1/thread)
        {
            int row = tid >> 2, seg = tid & 3;
            int kf = k0 + seg * 4;
            int gr = ctaRow0 + row;
            bool v = (kf + 4 <= INDIM) && (gr < NN);
            uint32_t dst = smem_u32(As + row * A_STRIDE) + seg * 16;
            cp16(dst, A + (v ? (size_t)gr * INDIM + kf : 0), v ? 16 : 0);
        }
        // B: 16 rows x 32 chunks of 16B -> 512 cp.async (2/thread)
#pragma unroll
        for (int j = 0; j < 2; j++) {
            int idx = tid + j * 256;
            int row = idx >> 5, seg = idx & 31;
            bool v = (k0 + row) < INDIM;
            uint32_t dst = smem_u32(Bs + row * B_STRIDE) + seg * 16;
            cp16(dst, B + (v ? (size_t)(k0 + row) * HID + n0 + seg * 4 : 0), v ? 16 : 0);
        }
    }
    asm volatile("cp.async.commit_group;" ::: "memory");
}

__global__ __launch_bounds__(256) void k_gemm_mma(const float* __restrict__ A,
                                                  const float* __restrict__ B) {
    __shared__ __align__(16) float sm[3 * STAGE_F];  // 41472 B
    int tid = threadIdx.x;
    int warp = tid >> 5, lane = tid & 31;
    int g = lane >> 2, tig = lane & 3;
    int wm = (warp >> 2) * 32;       // 0 or 32
    int wn = (warp & 3) * 32;        // 0..96
    int ctaRow0 = blockIdx.y * 64;
    int n0 = blockIdx.x * 128;

    float d[2][4][4];
#pragma unroll
    for (int mt = 0; mt < 2; mt++)
#pragma unroll
        for (int nt = 0; nt < 4; nt++)
#pragma unroll
            for (int r = 0; r < 4; r++) d[mt][nt][r] = 0.0f;

    // prologue: stages 0,1
    g1_load(sm, 0, ctaRow0, n0, A, B);
    g1_load(sm, 1, ctaRow0, n0, A, B);

    for (int c = 0; c < NCH; c++) {
        asm volatile("cp.async.wait_group 1;" ::: "memory");
        __syncthreads();
        g1_load(sm, c + 2, ctaRow0, n0, A, B);

        const float* As = sm + (c % 3) * STAGE_F;
        const float* Bs = As + A_FLOATS;
#pragma unroll
        for (int ks = 0; ks < 2; ks++) {
            int kb = ks * 8;
            uint32_t af[2][4], bf[4][2];
#pragma unroll
            for (int mt = 0; mt < 2; mt++) {
                int m = wm + mt * 16 + g;
                af[mt][0] = tf32r(As[m * A_STRIDE + kb + tig]);
                af[mt][1] = tf32r(As[(m + 8) * A_STRIDE + kb + tig]);
                af[mt][2] = tf32r(As[m * A_STRIDE + kb + tig + 4]);
                af[mt][3] = tf32r(As[(m + 8) * A_STRIDE + kb + tig + 4]);
            }
#pragma unroll
            for (int nt = 0; nt < 4; nt++) {
                int n = wn + nt * 8 + g;
                bf[nt][0] = tf32r(Bs[(kb + tig) * B_STRIDE + n]);
                bf[nt][1] = tf32r(Bs[(kb + tig + 4) * B_STRIDE + n]);
            }
#pragma unroll
            for (int mt = 0; mt < 2; mt++)
#pragma unroll
                for (int nt = 0; nt < 4; nt++)
                    mma_tf32(d[mt][nt], af[mt], bf[nt]);
        }
        __syncthreads();
    }

    // epilogue: registers -> g_xw1
#pragma unroll
    for (int mt = 0; mt < 2; mt++) {
        int row0 = ctaRow0 + wm + mt * 16 + g;
#pragma unroll
        for (int nt = 0; nt < 4; nt++) {
            int col = n0 + wn + nt * 8 + 2 * tig;
            if (row0 < NN)
                *(float2*)&g_xw1[(size_t)row0 * HID + col] =
                    make_float2(d[mt][nt][0], d[mt][nt][1]);
            if (row0 + 8 < NN)
                *(float2*)&g_xw1[(size_t)(row0 + 8) * HID + col] =
                    make_float2(d[mt][nt][2], d[mt][nt][3]);
        }
    }
}

// ---------------- agg1 + bias + relu -> g_h (warp per node) ----------------
__global__ void k_agg1(const float* __restrict__ b1) {
    int w = (blockIdx.x * blockDim.x + threadIdx.x) >> 5;
    int lane = threadIdx.x & 31;
    if (w >= NN) return;
    int i = w;
    float di = g_dinv[i];
    float acc[8];
    const float* xi = g_xw1 + (size_t)i * HID;
#pragma unroll
    for (int u = 0; u < 8; u++) acc[u] = di * xi[u * 32 + lane];
    int p0 = g_off[i], p1 = g_off[i + 1];
    for (int p = p0; p < p1; p++) {
        int s = g_srcv[p];
        float ds = g_dinv[s];
        const float* xs = g_xw1 + (size_t)s * HID;
#pragma unroll
        for (int u = 0; u < 8; u++) acc[u] += ds * xs[u * 32 + lane];
    }
    float* hi = g_h + (size_t)i * HID;
#pragma unroll
    for (int u = 0; u < 8; u++) {
        int f = u * 32 + lane;
        hi[f] = fmaxf(fmaf(di, acc[u], b1[f]), 0.0f);
    }
}

// ---------------- h @ W2 -> g_hw2 (warp per node) ----------------
__global__ void k_hw2(const float* __restrict__ W2) {
    int w = (blockIdx.x * blockDim.x + threadIdx.x) >> 5;
    int lane = threadIdx.x & 31;
    if (w >= NN) return;
    const float* hi = g_h + (size_t)w * HID;
    float a0 = 0.f, a1 = 0.f;
#pragma unroll
    for (int u = 0; u < 8; u++) {
        int k = u * 32 + lane;
        float hv = hi[k];
        a0 = fmaf(hv, W2[k * 2 + 0], a0);
        a1 = fmaf(hv, W2[k * 2 + 1], a1);
    }
#pragma unroll
    for (int o = 16; o > 0; o >>= 1) {
        a0 += __shfl_down_sync(0xffffffffu, a0, o);
        a1 += __shfl_down_sync(0xffffffffu, a1, o);
    }
    if (lane == 0) {
        g_hw2[w * 2 + 0] = a0;
        g_hw2[w * 2 + 1] = a1;
    }
}

// ---------------- agg2 + bias -> emb (d_out) and sq ----------------
__global__ void k_agg2(const float* __restrict__ b2, float* __restrict__ emb) {
    int i = blockIdx.x * blockDim.x + threadIdx.x;
    if (i >= NN) return;
    float di = g_dinv[i];
    float a0 = di * g_hw2[i * 2 + 0];
    float a1 = di * g_hw2[i * 2 + 1];
    int p0 = g_off[i], p1 = g_off[i + 1];
    for (int p = p0; p < p1; p++) {
        int s = g_srcv[p];
        float ds = g_dinv[s];
        a0 = fmaf(ds, g_hw2[s * 2 + 0], a0);
        a1 = fmaf(ds, g_hw2[s * 2 + 1], a1);
    }
    float e0 = fmaf(di, a0, b2[0]);
    float e1 = fmaf(di, a1, b2[1]);
    emb[i * 2 + 0] = e0;
    emb[i * 2 + 1] = e1;
    g_sq[i] = e0 * e0 + e1 * e1;
}

// ---------------- q matrix: q = 1/(1 + 0.5*dist) ----------------
#define TJ 1024
#define TI 16

__device__ __forceinline__ float qval(float d2) {
    float d2c = fmaxf(d2, 1e-30f);
    float dist = d2c * rsqrtf(d2c);
    return __fdividef(1.0f, fmaf(0.5f, dist, 1.0f));
}

__global__ __launch_bounds__(256) void k_q(const float* __restrict__ emb,
                                           float* __restrict__ q) {
    __shared__ float sx[TJ], sy[TJ], ss[TJ];
    int j0 = blockIdx.x * TJ;
    int i0 = blockIdx.y * TI;
    int t = threadIdx.x;
#pragma unroll
    for (int v = 0; v < 4; v++) {
        int jl = t + v * 256;
        int jj = j0 + jl;
        if (jj < NN) {
            sx[jl] = emb[jj * 2 + 0];
            sy[jl] = emb[jj * 2 + 1];
            ss[jl] = g_sq[jj];
        }
    }
    __syncthreads();
    int jl = t * 4;
    int j = j0 + jl;
    if (j >= NN) return;
    float x0 = sx[jl], x1 = sx[jl + 1], x2 = sx[jl + 2], x3 = sx[jl + 3];
    float y0 = sy[jl], y1 = sy[jl + 1], y2 = sy[jl + 2], y3 = sy[jl + 3];
    float s0 = ss[jl], s1 = ss[jl + 1], s2 = ss[jl + 2], s3 = ss[jl + 3];
#pragma unroll
    for (int r = 0; r < TI; r++) {
        int i = i0 + r;
        float ex = emb[i * 2 + 0];
        float ey = emb[i * 2 + 1];
        float si = g_sq[i];
        float4 o;
        o.x = qval(si + s0 - 2.0f * fmaf(ex, x0, ey * y0));
        o.y = qval(si + s1 - 2.0f * fmaf(ex, x1, ey * y1));
        o.z = qval(si + s2 - 2.0f * fmaf(ex, x2, ey * y2));
        o.w = qval(si + s3 - 2.0f * fmaf(ex, x3, ey * y3));
        *(float4*)(q + (size_t)i * NN + j) = o;
    }
}

// ---------------- launch ----------------
extern "C" void kernel_launch(void* const* d_in, const int* in_sizes, int n_in,
                              void* d_out, int out_size) {
    const float* features = (const float*)d_in[0];
    const int*   ei       = (const int*)d_in[1];
    const float* W1       = (const float*)d_in[2];
    const float* b1       = (const float*)d_in[3];
    const float* W2       = (const float*)d_in[4];
    const float* b2       = (const float*)d_in[5];
    float* out = (float*)d_out;
    float* emb = out;                 // [NN, 2]
    float* q   = out + NN * OUTD;     // [NN, NN]

    k_zero_deg<<<(NN + 255) / 256, 256>>>();
    k_count<<<(EE + 255) / 256, 256>>>(ei);
    k_scan<<<1, 256>>>();
    k_scatter<<<(EE + 255) / 256, 256>>>(ei);

    dim3 gg(HID / 128, (NN + 63) / 64);  // (2, 157)
    k_gemm_mma<<<gg, 256>>>(features, W1);

    k_agg1<<<(NN * 32 + 255) / 256, 256>>>(b1);
    k_hw2<<<(NN * 32 + 255) / 256, 256>>>(W2);
    k_agg2<<<(NN + 255) / 256, 256>>>(b2, emb);

    dim3 gq((NN + TJ - 1) / TJ, NN / TI);
    k_q<<<gq, 256>>>(emb, q);
}

// round 7
// speedup vs baseline: 2.8937x; 1.0294x over previous
#include <cuda_runtime.h>
#include <cstdint>

#define NN    10000
#define EE    160000
#define INDIM 1000
#define HID   256
#define OUTD  2

// ---------------- scratch (static __device__, no runtime alloc) ----------------
__device__ float g_xw1[NN * HID];   // features @ W1
__device__ float g_hw2[NN * OUTD];  // relu(gcn1) @ W2
__device__ float g_dinv[NN];
__device__ float g_sq[NN];
__device__ int   g_deg[NN];
__device__ int   g_cur[NN];
__device__ int   g_off[NN + 1];
__device__ int   g_srcv[EE];

// ================= helpers =================
__device__ __forceinline__ uint32_t smem_u32(const void* p) {
    uint32_t a;
    asm("{ .reg .u64 t; cvta.to.shared.u64 t, %1; cvt.u32.u64 %0, t; }"
        : "=r"(a) : "l"(p));
    return a;
}

__device__ __forceinline__ void cp16(uint32_t dst, const void* src, int sz) {
    asm volatile("cp.async.cg.shared.global [%0], [%1], 16, %2;"
                 :: "r"(dst), "l"(src), "r"(sz) : "memory");
}

__device__ __forceinline__ uint32_t tf32r(float x) {
    uint32_t u;
    asm("cvt.rna.tf32.f32 %0, %1;" : "=r"(u) : "f"(x));
    return u;
}

__device__ __forceinline__ void mma_tf32(float* d, const uint32_t* a, const uint32_t* b) {
    asm volatile(
        "mma.sync.aligned.m16n8k8.row.col.f32.tf32.tf32.f32 "
        "{%0,%1,%2,%3}, {%4,%5,%6,%7}, {%8,%9}, {%0,%1,%2,%3};"
        : "+f"(d[0]), "+f"(d[1]), "+f"(d[2]), "+f"(d[3])
        : "r"(a[0]), "r"(a[1]), "r"(a[2]), "r"(a[3]), "r"(b[0]), "r"(b[1]));
}

// ---------------- CSR build ----------------
__global__ void k_zero_deg() {
    int i = blockIdx.x * blockDim.x + threadIdx.x;
    if (i < NN) g_deg[i] = 0;
}

__global__ void k_count(const int* __restrict__ ei) {
    int i = blockIdx.x * blockDim.x + threadIdx.x;
    if (i < EE / 4) {
        int4 d = ((const int4*)(ei + EE))[i];
        atomicAdd(&g_deg[d.x], 1);
        atomicAdd(&g_deg[d.y], 1);
        atomicAdd(&g_deg[d.z], 1);
        atomicAdd(&g_deg[d.w], 1);
    }
}

__global__ void k_scan() {
    __shared__ int part[256];
    __shared__ int excl[257];
    int t = threadIdx.x;
    const int CH = (NN + 255) / 256;
    int base = t * CH;
    int s = 0;
    for (int i = 0; i < CH; i++) {
        int idx = base + i;
        if (idx < NN) s += g_deg[idx];
    }
    part[t] = s;
    __syncthreads();
    if (t == 0) {
        int run = 0;
        for (int i = 0; i < 256; i++) { excl[i] = run; run += part[i]; }
        excl[256] = run;
    }
    __syncthreads();
    int off = excl[t];
    for (int i = 0; i < CH; i++) {
        int idx = base + i;
        if (idx < NN) {
            g_off[idx] = off;
            g_cur[idx] = off;
            int d = g_deg[idx];
            off += d;
            g_dinv[idx] = rsqrtf((float)(d + 1));
        }
    }
    if (t == 255) g_off[NN] = excl[256];
}

__global__ void k_scatter(const int* __restrict__ ei) {
    int i = blockIdx.x * blockDim.x + threadIdx.x;
    if (i < EE / 4) {
        int4 sv = ((const int4*)ei)[i];
        int4 dv = ((const int4*)(ei + EE))[i];
        g_srcv[atomicAdd(&g_cur[dv.x], 1)] = sv.x;
        g_srcv[atomicAdd(&g_cur[dv.y], 1)] = sv.y;
        g_srcv[atomicAdd(&g_cur[dv.z], 1)] = sv.z;
        g_srcv[atomicAdd(&g_cur[dv.w], 1)] = sv.w;
    }
}

// ---------------- GEMM1 via mma.sync tf32: features[10000,1000] @ W1[1000,256] ----------------
#define A_STRIDE 20
#define B_STRIDE 136
#define A_FLOATS (64 * A_STRIDE)
#define STAGE_F  (A_FLOATS + 16 * B_STRIDE)
#define NCH      63

__device__ __forceinline__ void g1_load(float* smbase, int c, int ctaRow0, int n0,
                                        const float* __restrict__ A,
                                        const float* __restrict__ B) {
    if (c < NCH) {
        int k0 = c * 16;
        float* As = smbase + (c % 3) * STAGE_F;
        float* Bs = As + A_FLOATS;
        int tid = threadIdx.x;
        {
            int row = tid >> 2, seg = tid & 3;
            int kf = k0 + seg * 4;
            int gr = ctaRow0 + row;
            bool v = (kf + 4 <= INDIM) && (gr < NN);
            uint32_t dst = smem_u32(As + row * A_STRIDE) + seg * 16;
            cp16(dst, A + (v ? (size_t)gr * INDIM + kf : 0), v ? 16 : 0);
        }
#pragma unroll
        for (int j = 0; j < 2; j++) {
            int idx = tid + j * 256;
            int row = idx >> 5, seg = idx & 31;
            bool v = (k0 + row) < INDIM;
            uint32_t dst = smem_u32(Bs + row * B_STRIDE) + seg * 16;
            cp16(dst, B + (v ? (size_t)(k0 + row) * HID + n0 + seg * 4 : 0), v ? 16 : 0);
        }
    }
    asm volatile("cp.async.commit_group;" ::: "memory");
}

__global__ __launch_bounds__(256) void k_gemm_mma(const float* __restrict__ A,
                                                  const float* __restrict__ B) {
    __shared__ __align__(16) float sm[3 * STAGE_F];
    int tid = threadIdx.x;
    int warp = tid >> 5, lane = tid & 31;
    int g = lane >> 2, tig = lane & 3;
    int wm = (warp >> 2) * 32;
    int wn = (warp & 3) * 32;
    int ctaRow0 = blockIdx.y * 64;
    int n0 = blockIdx.x * 128;

    float d[2][4][4];
#pragma unroll
    for (int mt = 0; mt < 2; mt++)
#pragma unroll
        for (int nt = 0; nt < 4; nt++)
#pragma unroll
            for (int r = 0; r < 4; r++) d[mt][nt][r] = 0.0f;

    g1_load(sm, 0, ctaRow0, n0, A, B);
    g1_load(sm, 1, ctaRow0, n0, A, B);

    for (int c = 0; c < NCH; c++) {
        asm volatile("cp.async.wait_group 1;" ::: "memory");
        __syncthreads();
        g1_load(sm, c + 2, ctaRow0, n0, A, B);

        const float* As = sm + (c % 3) * STAGE_F;
        const float* Bs = As + A_FLOATS;
#pragma unroll
        for (int ks = 0; ks < 2; ks++) {
            int kb = ks * 8;
            uint32_t af[2][4], bf[4][2];
#pragma unroll
            for (int mt = 0; mt < 2; mt++) {
                int m = wm + mt * 16 + g;
                af[mt][0] = tf32r(As[m * A_STRIDE + kb + tig]);
                af[mt][1] = tf32r(As[(m + 8) * A_STRIDE + kb + tig]);
                af[mt][2] = tf32r(As[m * A_STRIDE + kb + tig + 4]);
                af[mt][3] = tf32r(As[(m + 8) * A_STRIDE + kb + tig + 4]);
            }
#pragma unroll
            for (int nt = 0; nt < 4; nt++) {
                int n = wn + nt * 8 + g;
                bf[nt][0] = tf32r(Bs[(kb + tig) * B_STRIDE + n]);
                bf[nt][1] = tf32r(Bs[(kb + tig + 4) * B_STRIDE + n]);
            }
#pragma unroll
            for (int mt = 0; mt < 2; mt++)
#pragma unroll
                for (int nt = 0; nt < 4; nt++)
                    mma_tf32(d[mt][nt], af[mt], bf[nt]);
        }
        __syncthreads();
    }

#pragma unroll
    for (int mt = 0; mt < 2; mt++) {
        int row0 = ctaRow0 + wm + mt * 16 + g;
#pragma unroll
        for (int nt = 0; nt < 4; nt++) {
            int col = n0 + wn + nt * 8 + 2 * tig;
            if (row0 < NN)
                *(float2*)&g_xw1[(size_t)row0 * HID + col] =
                    make_float2(d[mt][nt][0], d[mt][nt][1]);
            if (row0 + 8 < NN)
                *(float2*)&g_xw1[(size_t)(row0 + 8) * HID + col] =
                    make_float2(d[mt][nt][2], d[mt][nt][3]);
        }
    }
}

// ---------------- fused agg1 + bias + relu + W2 projection -> g_hw2 ----------------
__global__ void k_agg1(const float* __restrict__ b1, const float* __restrict__ W2) {
    int w = (blockIdx.x * blockDim.x + threadIdx.x) >> 5;
    int lane = threadIdx.x & 31;
    if (w >= NN) return;
    float di = g_dinv[w];
    float acc[8];
    const float* xi = g_xw1 + (size_t)w * HID;
#pragma unroll
    for (int u = 0; u < 8; u++) acc[u] = di * xi[u * 32 + lane];
    int p0 = g_off[w], p1 = g_off[w + 1];
    for (int p = p0; p < p1; p++) {
        int s = g_srcv[p];
        float ds = g_dinv[s];
        const float* xs = g_xw1 + (size_t)s * HID;
#pragma unroll
        for (int u = 0; u < 8; u++) acc[u] = fmaf(ds, xs[u * 32 + lane], acc[u]);
    }
    float a0 = 0.f, a1 = 0.f;
#pragma unroll
    for (int u = 0; u < 8; u++) {
        int f = u * 32 + lane;
        float h = fmaxf(fmaf(di, acc[u], b1[f]), 0.0f);
        a0 = fmaf(h, W2[f * 2 + 0], a0);
        a1 = fmaf(h, W2[f * 2 + 1], a1);
    }
#pragma unroll
    for (int o = 16; o > 0; o >>= 1) {
        a0 += __shfl_down_sync(0xffffffffu, a0, o);
        a1 += __shfl_down_sync(0xffffffffu, a1, o);
    }
    if (lane == 0) {
        g_hw2[w * 2 + 0] = a0;
        g_hw2[w * 2 + 1] = a1;
    }
}

// ---------------- agg2 + bias -> emb (d_out) and sq ----------------
__global__ void k_agg2(const float* __restrict__ b2, float* __restrict__ emb) {
    int i = blockIdx.x * blockDim.x + threadIdx.x;
    if (i >= NN) return;
    float di = g_dinv[i];
    float a0 = di * g_hw2[i * 2 + 0];
    float a1 = di * g_hw2[i * 2 + 1];
    int p0 = g_off[i], p1 = g_off[i + 1];
    for (int p = p0; p < p1; p++) {
        int s = g_srcv[p];
        float ds = g_dinv[s];
        a0 = fmaf(ds, g_hw2[s * 2 + 0], a0);
        a1 = fmaf(ds, g_hw2[s * 2 + 1], a1);
    }
    float e0 = fmaf(di, a0, b2[0]);
    float e1 = fmaf(di, a1, b2[1]);
    emb[i * 2 + 0] = e0;
    emb[i * 2 + 1] = e1;
    g_sq[i] = e0 * e0 + e1 * e1;
}

// ---------------- symmetric q: compute tile-pairs (bi<=bj), mirror via smem ----------------
#define QT     96
#define QTILES 105   // ceil(10000/96)

__device__ __forceinline__ float qval(float d2) {
    float d2c = fmaxf(d2, 1e-30f);
    float dist = d2c * rsqrtf(d2c);
    return __fdividef(1.0f, fmaf(0.5f, dist, 1.0f));
}

__global__ __launch_bounds__(256) void k_qsym(const float* __restrict__ emb,
                                              float* __restrict__ q) {
    __shared__ float sjx[QT], sjy[QT], sjs[QT];
    __shared__ float six[QT], siy[QT], sis[QT];
    __shared__ float tile[QT][QT + 1];   // stride 97: conflict-free both ways
    int bj = blockIdx.x, bi = blockIdx.y;
    if (bi > bj) return;
    int i0 = bi * QT, j0 = bj * QT;
    int t = threadIdx.x;
    if (t < QT) {
        int jj = min(j0 + t, NN - 1);
        sjx[t] = emb[jj * 2 + 0]; sjy[t] = emb[jj * 2 + 1]; sjs[t] = g_sq[jj];
        int ii = min(i0 + t, NN - 1);
        six[t] = emb[ii * 2 + 0]; siy[t] = emb[ii * 2 + 1]; sis[t] = g_sq[ii];
    }
    __syncthreads();
    int warp = t >> 5, lane = t & 31;
    bool diag = (bi == bj);

    float jx[3], jy[3], js[3];
#pragma unroll
    for (int v = 0; v < 3; v++) {
        int c = lane + 32 * v;
        jx[v] = sjx[c]; jy[v] = sjy[c]; js[v] = sjs[c];
    }

#pragma unroll
    for (int rr = 0; rr < 12; rr++) {
        int r = warp * 12 + rr;
        float ix = six[r], iy = siy[r], si = sis[r];
        int gi = i0 + r;
        bool rowok = gi < NN;
#pragma unroll
        for (int v = 0; v < 3; v++) {
            int c = lane + 32 * v;
            float qv = qval(si + js[v] - 2.0f * fmaf(ix, jx[v], iy * jy[v]));
            tile[r][c] = qv;
            int gj = j0 + c;
            if (rowok && gj < NN) q[(size_t)gi * NN + gj] = qv;
        }
    }
    if (diag) return;
    __syncthreads();
    // mirrored block: row gj = j0+c, cols i0+r (coalesced over lane)
#pragma unroll
    for (int cc = 0; cc < 12; cc++) {
        int c = warp * 12 + cc;
        int gj = j0 + c;
        if (gj >= NN) continue;
        float* qrow = q + (size_t)gj * NN + i0;
#pragma unroll
        for (int v = 0; v < 3; v++) {
            int r = lane + 32 * v;
            if (i0 + r < NN) qrow[r] = tile[r][c];
        }
    }
}

// ---------------- launch ----------------
extern "C" void kernel_launch(void* const* d_in, const int* in_sizes, int n_in,
                              void* d_out, int out_size) {
    const float* features = (const float*)d_in[0];
    const int*   ei       = (const int*)d_in[1];
    const float* W1       = (const float*)d_in[2];
    const float* b1       = (const float*)d_in[3];
    const float* W2       = (const float*)d_in[4];
    const float* b2       = (const float*)d_in[5];
    float* out = (float*)d_out;
    float* emb = out;                 // [NN, 2]
    float* q   = out + NN * OUTD;     // [NN, NN]

    k_zero_deg<<<(NN + 255) / 256, 256>>>();
    k_count<<<(EE / 4 + 255) / 256, 256>>>(ei);
    k_scan<<<1, 256>>>();
    k_scatter<<<(EE / 4 + 255) / 256, 256>>>(ei);

    dim3 gg(HID / 128, (NN + 63) / 64);  // (2, 157)
    k_gemm_mma<<<gg, 256>>>(features, W1);

    k_agg1<<<(NN * 32 + 255) / 256, 256>>>(b1, W2);
    k_agg2<<<(NN + 255) / 256, 256>>>(b2, emb);

    dim3 gq(QTILES, QTILES);
    k_qsym<<<gq, 256>>>(emb, q);
}